// round 2
// baseline (speedup 1.0000x reference)
#include <cuda_runtime.h>
#include <cuda_bf16.h>
#include <math.h>

// Problem constants
#define BB 8
#define CC 128
#define HH 512
#define WW 512
#define HW (HH*WW)
#define KK 64
#define BK (BB*KK)      // 512 samples
#define NNEG 7
#define PP 4096
#define TAU 0.07f

// Tiling for sim GEMM
#define TQ 32           // queries per block
#define TP 128          // pool rows per block
#define NQT (BK/TQ)     // 16
#define NPT (PP/TP)     // 32

// Scratch (device globals; no allocation)
__device__ float g_qnorm[BK*CC];       // normalized query pixels
__device__ float g_pinv[PP];           // 1/||pool_p||
__device__ float g_pmax[BK*NPT];       // per-tile max sim
__device__ int   g_pidx[BK*NPT];       // per-tile argmax (global p)
__device__ float g_loss[BK];           // per-sample loss

__device__ __forceinline__ float dot4(float4 a, float4 b) {
    return a.x*b.x + a.y*b.y + a.z*b.z + a.w*b.w;
}

// ---------------------------------------------------------------------------
// K0: pool inverse norms. One thread per pool row.
// ---------------------------------------------------------------------------
__global__ void k_pool_inv(const float* __restrict__ pool) {
    int p = blockIdx.x * blockDim.x + threadIdx.x;
    if (p >= PP) return;
    const float4* row = (const float4*)(pool + (size_t)p * CC);
    float ss = 0.f;
#pragma unroll
    for (int i = 0; i < CC/4; i++) {
        float4 v = row[i];
        ss += dot4(v, v);
    }
    g_pinv[p] = 1.0f / fmaxf(sqrtf(ss), 1e-12f);
}

// ---------------------------------------------------------------------------
// K1: gather sampled query pixels (strided) + L2 normalize. Warp per sample.
// ---------------------------------------------------------------------------
__global__ void k_gather_norm(const float* __restrict__ qf,
                              const int* __restrict__ qidx) {
    int w = threadIdx.x >> 5, lane = threadIdx.x & 31;
    int gq = blockIdx.x * 8 + w;              // 64 blocks * 8 warps = 512
    int b = gq >> 6;
    int idx = qidx[gq];
    int c0 = lane * 4;
    const float* base = qf + ((size_t)b * CC) * HW + idx;
    float v0 = base[(size_t)(c0+0) * HW];
    float v1 = base[(size_t)(c0+1) * HW];
    float v2 = base[(size_t)(c0+2) * HW];
    float v3 = base[(size_t)(c0+3) * HW];
    float ss = v0*v0 + v1*v1 + v2*v2 + v3*v3;
#pragma unroll
    for (int off = 16; off; off >>= 1)
        ss += __shfl_xor_sync(0xffffffffu, ss, off);
    float inv = 1.0f / fmaxf(sqrtf(ss), 1e-12f);
    float4 o = make_float4(v0*inv, v1*inv, v2*inv, v3*inv);
    *((float4*)(g_qnorm + (size_t)gq * CC + c0)) = o;
}

// ---------------------------------------------------------------------------
// K2: sim = q_norm @ pool_norm^T with per-(query, p-tile) argmax.
// Block: 256 threads, tile TQ=32 x TP=128, K=128.
// Thread micro-tile 4q x 4p.  Warp = one q-group (4 queries), lanes = p-groups.
// Pool smem uses XOR swizzle keyed on (row>>2)&7 -> conflict-free LDS.128.
// ---------------------------------------------------------------------------
__global__ void k_sim_argmax(const float* __restrict__ pool) {
    extern __shared__ float sm[];
    float4* sQ = (float4*)sm;                    // 32 rows x 32 float4
    float4* sP = (float4*)(sm + TQ*CC);          // 128 rows x 32 float4 (swizzled)

    int qt = blockIdx.x, pt = blockIdx.y;
    int qBase = qt * TQ, pBase = pt * TP;
    int tid = threadIdx.x;

    // Load Q tile: 1024 float4, 4 per thread, coalesced.
    {
        const float4* src = (const float4*)(g_qnorm + (size_t)qBase * CC);
#pragma unroll
        for (int i = 0; i < 4; i++)
            sQ[tid + i*256] = src[tid + i*256];
    }
    // Load P tile with swizzle: warp w loads rows w*16..w*16+15, lane = c4.
    {
        int lane = tid & 31, w = tid >> 5;
#pragma unroll
        for (int rr = 0; rr < 16; rr++) {
            int row = w * 16 + rr;
            float4 v = ((const float4*)(pool + (size_t)(pBase + row) * CC))[lane];
            int sw = (row >> 2) & 7;
            sP[row * 32 + (lane ^ sw)] = v;
        }
    }
    __syncthreads();

    int pg = tid & 31;        // p-group: 4 rows starting 4*pg
    int qg = tid >> 5;        // q-group: 4 rows starting 4*qg (warp-uniform)
    int sw = pg & 7;          // swizzle for rows 4*pg..4*pg+3 ((r>>2)&7 == pg&7... for r>>2==pg)

    float acc[4][4];
#pragma unroll
    for (int i = 0; i < 4; i++)
#pragma unroll
        for (int j = 0; j < 4; j++) acc[i][j] = 0.f;

#pragma unroll 4
    for (int c4 = 0; c4 < 32; c4++) {
        float4 a[4], b[4];
#pragma unroll
        for (int i = 0; i < 4; i++)
            a[i] = sQ[(4*qg + i) * 32 + c4];            // broadcast within warp
#pragma unroll
        for (int j = 0; j < 4; j++)
            b[j] = sP[(4*pg + j) * 32 + (c4 ^ sw)];      // conflict-free
#pragma unroll
        for (int i = 0; i < 4; i++)
#pragma unroll
            for (int j = 0; j < 4; j++) {
                acc[i][j] += a[i].x*b[j].x;
                acc[i][j] += a[i].y*b[j].y;
                acc[i][j] += a[i].z*b[j].z;
                acc[i][j] += a[i].w*b[j].w;
            }
    }

    // Scale by pool inv-norm, per-query argmax across this p-tile.
    float pin[4];
#pragma unroll
    for (int j = 0; j < 4; j++) pin[j] = g_pinv[pBase + 4*pg + j];

#pragma unroll
    for (int i = 0; i < 4; i++) {
        float best = -1e30f; int bidx = 0;
#pragma unroll
        for (int j = 0; j < 4; j++) {
            float v = acc[i][j] * pin[j];
            int p = pBase + 4*pg + j;
            if (v > best) { best = v; bidx = p; }
        }
#pragma unroll
        for (int off = 16; off; off >>= 1) {
            float ov = __shfl_xor_sync(0xffffffffu, best, off);
            int   oi = __shfl_xor_sync(0xffffffffu, bidx, off);
            if (ov > best || (ov == best && oi < bidx)) { best = ov; bidx = oi; }
        }
        if (pg == 0) {
            int gq = qBase + 4*qg + i;
            g_pmax[gq * NPT + pt] = best;
            g_pidx[gq * NPT + pt] = bidx;
        }
    }
}

// ---------------------------------------------------------------------------
// K3: per-sample loss. Warp per sample. Merge tile argmaxes, compute positive
// and negative cosine logits, log-softmax CE (label 0).
// ---------------------------------------------------------------------------
__global__ void k_loss(const float* __restrict__ pool,
                       const float* __restrict__ negs) {
    int w = threadIdx.x >> 5, lane = threadIdx.x & 31;
    int gq = blockIdx.x * 8 + w;

    // Global argmax over 32 tiles (tie -> smallest p == jnp first occurrence).
    float v = g_pmax[gq * NPT + lane];
    int idx = g_pidx[gq * NPT + lane];
#pragma unroll
    for (int off = 16; off; off >>= 1) {
        float ov = __shfl_xor_sync(0xffffffffu, v, off);
        int   oi = __shfl_xor_sync(0xffffffffu, idx, off);
        if (ov > v || (ov == v && oi < idx)) { v = ov; idx = oi; }
    }
    int pstar = idx;

    float4 q = ((const float4*)(g_qnorm + (size_t)gq * CC))[lane];

    float l[NNEG + 1];
    // positive
    {
        float4 pp = ((const float4*)(pool + (size_t)pstar * CC))[lane];
        float d = dot4(q, pp);
#pragma unroll
        for (int off = 16; off; off >>= 1)
            d += __shfl_xor_sync(0xffffffffu, d, off);
        l[0] = (d * g_pinv[pstar]) / TAU;
    }
    // negatives
#pragma unroll
    for (int n = 0; n < NNEG; n++) {
        float4 nv = ((const float4*)(negs + ((size_t)gq * NNEG + n) * CC))[lane];
        float pd = dot4(q, nv);
        float ps = dot4(nv, nv);
#pragma unroll
        for (int off = 16; off; off >>= 1) {
            pd += __shfl_xor_sync(0xffffffffu, pd, off);
            ps += __shfl_xor_sync(0xffffffffu, ps, off);
        }
        l[n + 1] = (pd / fmaxf(sqrtf(ps), 1e-12f)) / TAU;
    }

    if (lane == 0) {
        float m = l[0];
#pragma unroll
        for (int n = 1; n <= NNEG; n++) m = fmaxf(m, l[n]);
        float se = 0.f;
#pragma unroll
        for (int n = 0; n <= NNEG; n++) se += expf(l[n] - m);
        g_loss[gq] = logf(se) - (l[0] - m);
    }
}

// ---------------------------------------------------------------------------
// K4: deterministic mean over 512 samples.
// ---------------------------------------------------------------------------
__global__ void k_mean(float* __restrict__ out) {
    __shared__ float s[512];
    int t = threadIdx.x;
    s[t] = g_loss[t];
    __syncthreads();
#pragma unroll
    for (int off = 256; off; off >>= 1) {
        if (t < off) s[t] += s[t + off];
        __syncthreads();
    }
    if (t == 0) out[0] = s[0] / (float)BK;
}

// ---------------------------------------------------------------------------
extern "C" void kernel_launch(void* const* d_in, const int* in_sizes, int n_in,
                              void* d_out, int out_size) {
    const float* qf   = (const float*)d_in[0];   // [B,C,H,W]
    const float* pool = (const float*)d_in[1];   // [P,C]
    const float* negs = (const float*)d_in[2];   // [B,K,N,C]
    const int*   qidx = (const int*)d_in[3];     // [B,K]
    float* out = (float*)d_out;

    const int smem = (TQ*CC + TP*CC) * (int)sizeof(float);   // 80 KB
    cudaFuncSetAttribute(k_sim_argmax,
                         cudaFuncAttributeMaxDynamicSharedMemorySize, smem);

    k_pool_inv<<<PP/256, 256>>>(pool);
    k_gather_norm<<<BK/8, 256>>>(qf, qidx);
    k_sim_argmax<<<dim3(NQT, NPT), 256, smem>>>(pool);
    k_loss<<<BK/8, 256>>>(pool, negs);
    k_mean<<<1, 512>>>(out);
}

// round 3
// speedup vs baseline: 1.2480x; 1.2480x over previous
#include <cuda_runtime.h>
#include <cuda_bf16.h>
#include <math.h>

// Problem constants
#define BB 8
#define CC 128
#define HH 512
#define WW 512
#define HW (HH*WW)
#define KK 64
#define BK (BB*KK)      // 512 samples
#define NNEG 7
#define PP 4096
#define TAU 0.07f

// Tiling for sim GEMM
#define TQ 64           // queries per block (8 warps x 8 q)
#define TP 128          // pool rows per block (32 lanes x 4 p)
#define NQT (BK/TQ)     // 8
#define NPT (PP/TP)     // 32

// Scratch (device globals; no allocation)
__device__ float g_qnorm[BK*CC];
__device__ float g_pinv[PP];
__device__ float g_pmax[BK*NPT];
__device__ int   g_pidx[BK*NPT];
__device__ unsigned long long g_sum;
__device__ unsigned int g_done;

__device__ __forceinline__ float dot4(float4 a, float4 b) {
    return a.x*b.x + a.y*b.y + a.z*b.z + a.w*b.w;
}

// packed dual-FMA: d.lo += a.lo*b.lo ; d.hi += a.hi*b.hi
__device__ __forceinline__ void fma2(unsigned long long& d,
                                     unsigned long long a,
                                     unsigned long long b) {
    asm("fma.rn.f32x2 %0, %1, %2, %0;" : "+l"(d) : "l"(a), "l"(b));
}

__device__ __forceinline__ float unpack_sum(unsigned long long v) {
    float2 f;
    asm("mov.b64 {%0, %1}, %2;" : "=f"(f.x), "=f"(f.y) : "l"(v));
    return f.x + f.y;
}

// ---------------------------------------------------------------------------
// K0 (fused): blocks 0..15 -> pool inverse norms; blocks 16..79 -> gather+norm
// Also resets the fixed-point loss accumulator.
// ---------------------------------------------------------------------------
__global__ void k_prep(const float* __restrict__ pool,
                       const float* __restrict__ qf,
                       const int* __restrict__ qidx) {
    if (blockIdx.x == 0 && threadIdx.x == 0) { g_sum = 0ULL; g_done = 0u; }

    if (blockIdx.x < 16) {
        int p = blockIdx.x * 256 + threadIdx.x;
        const float4* row = (const float4*)(pool + (size_t)p * CC);
        float ss = 0.f;
#pragma unroll
        for (int i = 0; i < CC/4; i++) {
            float4 v = row[i];
            ss += dot4(v, v);
        }
        g_pinv[p] = 1.0f / fmaxf(sqrtf(ss), 1e-12f);
    } else {
        int w = threadIdx.x >> 5, lane = threadIdx.x & 31;
        int gq = (blockIdx.x - 16) * 8 + w;          // 64 blocks * 8 warps = 512
        int b = gq >> 6;
        int idx = qidx[gq];
        int c0 = lane * 4;
        const float* base = qf + ((size_t)b * CC) * HW + idx;
        float v0 = base[(size_t)(c0+0) * HW];
        float v1 = base[(size_t)(c0+1) * HW];
        float v2 = base[(size_t)(c0+2) * HW];
        float v3 = base[(size_t)(c0+3) * HW];
        float ss = v0*v0 + v1*v1 + v2*v2 + v3*v3;
#pragma unroll
        for (int off = 16; off; off >>= 1)
            ss += __shfl_xor_sync(0xffffffffu, ss, off);
        float inv = 1.0f / fmaxf(sqrtf(ss), 1e-12f);
        float4 o = make_float4(v0*inv, v1*inv, v2*inv, v3*inv);
        *((float4*)(g_qnorm + (size_t)gq * CC + c0)) = o;
    }
}

// ---------------------------------------------------------------------------
// K1: sim = q_norm @ pool_norm^T with per-(query, p-tile) argmax.
// Block: 256 threads, tile TQ=64 x TP=128, K=128.
// Micro-tile: 8q x 4p per thread via fma.rn.f32x2 (even/odd c packed).
// ---------------------------------------------------------------------------
__global__ void __launch_bounds__(256, 2) k_sim_argmax(const float* __restrict__ pool) {
    extern __shared__ float sm[];
    float4* sQ = (float4*)sm;                    // 64 rows x 32 float4
    float4* sP = (float4*)(sm + TQ*CC);          // 128 rows x 32 float4 (swizzled)

    int qt = blockIdx.x, pt = blockIdx.y;
    int qBase = qt * TQ, pBase = pt * TP;
    int tid = threadIdx.x;
    int lane = tid & 31, w = tid >> 5;

    // Load Q tile: 2048 float4, 8 per thread, coalesced. No swizzle (broadcast reads).
    {
        const float4* src = (const float4*)(g_qnorm + (size_t)qBase * CC);
#pragma unroll
        for (int i = 0; i < 8; i++)
            sQ[tid + i*256] = src[tid + i*256];
    }
    // Load P tile with swizzle: warp w loads rows w*16..w*16+15, lane = c4.
    {
#pragma unroll
        for (int rr = 0; rr < 16; rr++) {
            int row = w * 16 + rr;
            float4 v = ((const float4*)(pool + (size_t)(pBase + row) * CC))[lane];
            int sw = (row >> 2) & 7;
            sP[row * 32 + (lane ^ sw)] = v;
        }
    }
    __syncthreads();

    const ulonglong2* sQv = (const ulonglong2*)sQ;
    const ulonglong2* sPv = (const ulonglong2*)sP;

    int sw = lane & 7;                 // swizzle key for rows 4*lane..4*lane+3
    int qrow0 = w * 8;                 // this warp's 8 query rows (warp-uniform)

    unsigned long long acc[8][4];
#pragma unroll
    for (int i = 0; i < 8; i++)
#pragma unroll
        for (int j = 0; j < 4; j++) acc[i][j] = 0ULL;

#pragma unroll 4
    for (int c4 = 0; c4 < 32; c4++) {
        ulonglong2 bv[4];
#pragma unroll
        for (int j = 0; j < 4; j++)
            bv[j] = sPv[(4*lane + j) * 32 + (c4 ^ sw)];   // conflict-free
#pragma unroll
        for (int i = 0; i < 8; i++) {
            ulonglong2 av = sQv[(qrow0 + i) * 32 + c4];   // warp broadcast
#pragma unroll
            for (int j = 0; j < 4; j++) {
                fma2(acc[i][j], av.x, bv[j].x);
                fma2(acc[i][j], av.y, bv[j].y);
            }
        }
    }

    // Scale by pool inv-norm, per-query argmax across this p-tile.
    float pin[4];
#pragma unroll
    for (int j = 0; j < 4; j++) pin[j] = g_pinv[pBase + 4*lane + j];

#pragma unroll
    for (int i = 0; i < 8; i++) {
        float best = -1e30f; int bidx = 0;
#pragma unroll
        for (int j = 0; j < 4; j++) {
            float v = unpack_sum(acc[i][j]) * pin[j];
            int p = pBase + 4*lane + j;
            if (v > best) { best = v; bidx = p; }
        }
#pragma unroll
        for (int off = 16; off; off >>= 1) {
            float ov = __shfl_xor_sync(0xffffffffu, best, off);
            int   oi = __shfl_xor_sync(0xffffffffu, bidx, off);
            if (ov > best || (ov == best && oi < bidx)) { best = ov; bidx = oi; }
        }
        if (lane == 0) {
            int gq = qBase + qrow0 + i;
            g_pmax[gq * NPT + pt] = best;
            g_pidx[gq * NPT + pt] = bidx;
        }
    }
}

// ---------------------------------------------------------------------------
// K2: per-sample loss. One block per sample, one warp per logit.
// Fixed-point (2^-36) deterministic global sum; last block writes the mean.
// ---------------------------------------------------------------------------
__global__ void k_loss(const float* __restrict__ pool,
                       const float* __restrict__ negs,
                       float* __restrict__ out) {
    int gq = blockIdx.x;
    int w = threadIdx.x >> 5, lane = threadIdx.x & 31;
    __shared__ float s_logit[8];

    float4 q = ((const float4*)(g_qnorm + (size_t)gq * CC))[lane];

    if (w == 0) {
        // merge the 32 per-tile argmaxes (tie -> smallest p, jnp first-occurrence)
        float v = g_pmax[gq * NPT + lane];
        int idx = g_pidx[gq * NPT + lane];
#pragma unroll
        for (int off = 16; off; off >>= 1) {
            float ov = __shfl_xor_sync(0xffffffffu, v, off);
            int   oi = __shfl_xor_sync(0xffffffffu, idx, off);
            if (ov > v || (ov == v && oi < idx)) { v = ov; idx = oi; }
        }
        int pstar = idx;  // present in all lanes after butterfly
        float4 pp = ((const float4*)(pool + (size_t)pstar * CC))[lane];
        float d = dot4(q, pp);
#pragma unroll
        for (int off = 16; off; off >>= 1)
            d += __shfl_xor_sync(0xffffffffu, d, off);
        if (lane == 0) s_logit[0] = (d * g_pinv[pstar]) / TAU;
    } else {
        int n = w - 1;
        float4 nv = ((const float4*)(negs + ((size_t)gq * NNEG + n) * CC))[lane];
        float pd = dot4(q, nv);
        float ps = dot4(nv, nv);
#pragma unroll
        for (int off = 16; off; off >>= 1) {
            pd += __shfl_xor_sync(0xffffffffu, pd, off);
            ps += __shfl_xor_sync(0xffffffffu, ps, off);
        }
        if (lane == 0) s_logit[w] = (pd / fmaxf(sqrtf(ps), 1e-12f)) / TAU;
    }
    __syncthreads();

    if (threadIdx.x == 0) {
        float l0 = s_logit[0];
        float m = l0;
#pragma unroll
        for (int n = 1; n <= NNEG; n++) m = fmaxf(m, s_logit[n]);
        float se = 0.f;
#pragma unroll
        for (int n = 0; n <= NNEG; n++) se += expf(s_logit[n] - m);
        float loss = logf(se) - (l0 - m);

        // deterministic fixed-point accumulation (loss >= 0, < ~32)
        unsigned long long qv =
            (unsigned long long)__double2ll_rn((double)loss * 68719476736.0);
        atomicAdd(&g_sum, qv);
        __threadfence();
        unsigned int done = atomicAdd(&g_done, 1u);
        if (done == (unsigned int)(gridDim.x - 1)) {
            unsigned long long s = atomicAdd(&g_sum, 0ULL);
            out[0] = (float)((double)s * (1.0 / 68719476736.0) / (double)BK);
        }
    }
}

// ---------------------------------------------------------------------------
extern "C" void kernel_launch(void* const* d_in, const int* in_sizes, int n_in,
                              void* d_out, int out_size) {
    const float* qf   = (const float*)d_in[0];   // [B,C,H,W]
    const float* pool = (const float*)d_in[1];   // [P,C]
    const float* negs = (const float*)d_in[2];   // [B,K,N,C]
    const int*   qidx = (const int*)d_in[3];     // [B,K]
    float* out = (float*)d_out;

    const int smem = (TQ*CC + TP*CC) * (int)sizeof(float);   // 96 KB
    cudaFuncSetAttribute(k_sim_argmax,
                         cudaFuncAttributeMaxDynamicSharedMemorySize, smem);

    k_prep<<<80, 256>>>(pool, qf, qidx);
    k_sim_argmax<<<dim3(NQT, NPT), 256, smem>>>(pool);
    k_loss<<<BK, 256>>>(pool, negs, out);
}

// round 6
// speedup vs baseline: 1.2492x; 1.0010x over previous
#include <cuda_runtime.h>
#include <cuda_bf16.h>
#include <math.h>

// Problem constants
#define BB 8
#define CC 128
#define HH 512
#define WW 512
#define HW (HH*WW)
#define KK 64
#define BK (BB*KK)      // 512 samples
#define NNEG 7
#define PP 4096
#define TAU 0.07f

// Tiling for sim GEMM
#define TQ 64           // queries per block (8 warps x 8 q)
#define TP 128          // pool rows per block (32 lanes x 4 p)
#define NQT (BK/TQ)     // 8
#define NPT (PP/TP)     // 32

#define FXS 4503599627370496.0      // 2^52
#define FXI 2.220446049250313e-16f  // 2^-52

// Scratch (device globals; no allocation)
__device__ float g_qraw[BK*CC];                 // gathered (un-normalized) query pixels
__device__ unsigned long long g_ssq[BK];        // fixed-point sum-of-squares per sample
__device__ float g_pinv[PP];
__device__ float g_pmax[BK*NPT];
__device__ int   g_pidx[BK*NPT];
__device__ unsigned long long g_sum;
__device__ unsigned int g_done;

__device__ __forceinline__ float dot4(float4 a, float4 b) {
    return a.x*b.x + a.y*b.y + a.z*b.z + a.w*b.w;
}

// packed dual-FMA: d.lo += a.lo*b.lo ; d.hi += a.hi*b.hi
__device__ __forceinline__ void fma2(unsigned long long& d,
                                     unsigned long long a,
                                     unsigned long long b) {
    asm("fma.rn.f32x2 %0, %1, %2, %0;" : "+l"(d) : "l"(a), "l"(b));
}

__device__ __forceinline__ float unpack_sum(unsigned long long v) {
    float2 f;
    asm("mov.b64 {%0, %1}, %2;" : "=f"(f.x), "=f"(f.y) : "l"(v));
    return f.x + f.y;
}

__device__ __forceinline__ float inv_from_ssq(unsigned long long s) {
    float ss = (float)(long long)s * FXI;
    return rsqrtf(fmaxf(ss, 1e-24f));
}

// ---------------------------------------------------------------------------
// K0 (fused): blocks 0..15 -> pool inverse norms.
//             blocks 16..271 -> page-coherent gather + fixed-point sumsq.
// Gather layout: warp = fixed (b, c) column (one 2MB page), lanes = 32
// consecutive samples of that image. TLB: 1 page/warp instead of 1 page/load.
// ---------------------------------------------------------------------------
__global__ void k_prep(const float* __restrict__ pool,
                       const float* __restrict__ qf,
                       const int* __restrict__ qidx) {
    if (blockIdx.x == 0 && threadIdx.x == 0) { g_sum = 0ULL; g_done = 0u; }

    if (blockIdx.x < 16) {
        int p = blockIdx.x * 256 + threadIdx.x;
        const float4* row = (const float4*)(pool + (size_t)p * CC);
        float ss = 0.f;
#pragma unroll
        for (int i = 0; i < CC/4; i++) {
            float4 v = row[i];
            ss += dot4(v, v);
        }
        g_pinv[p] = 1.0f / fmaxf(sqrtf(ss), 1e-12f);
    } else {
        int gb = blockIdx.x - 16;            // 0..255
        int co = gb & 15;                    // c-octet 0..15
        int sg = gb >> 4;                    // sample group 0..15
        int w = threadIdx.x >> 5, lane = threadIdx.x & 31;
        int c  = co * 8 + w;
        int gq = sg * 32 + lane;             // 32 consecutive samples, same image
        int b  = gq >> 6;
        int idx = qidx[gq];
        float v = qf[((size_t)b * CC + c) * HW + idx];
        g_qraw[gq * CC + c] = v;

        __shared__ float s[8][33];
        s[w][lane] = v * v;
        __syncthreads();
        if (w == 0) {
            float ss = s[0][lane];
#pragma unroll
            for (int j = 1; j < 8; j++) ss += s[j][lane];
            unsigned long long qv =
                (unsigned long long)__double2ll_rn((double)ss * FXS);
            atomicAdd(&g_ssq[gq], qv);
        }
    }
}

// ---------------------------------------------------------------------------
// K1: sim = q_norm @ pool_norm^T with per-(query, p-tile) argmax.
// Block: 256 threads, tile TQ=64 x TP=128, K=128.
// Micro-tile: 8q x 4p per thread via fma.rn.f32x2 (even/odd c packed).
// Q normalization folded into the smem load (inv from g_ssq).
// ---------------------------------------------------------------------------
__global__ void __launch_bounds__(256, 2) k_sim_argmax(const float* __restrict__ pool) {
    extern __shared__ float sm[];
    float4* sQ = (float4*)sm;                    // 64 rows x 32 float4
    float4* sP = (float4*)(sm + TQ*CC);          // 128 rows x 32 float4 (swizzled)
    __shared__ float s_inv[TQ];

    int qt = blockIdx.x, pt = blockIdx.y;
    int qBase = qt * TQ, pBase = pt * TP;
    int tid = threadIdx.x;
    int lane = tid & 31, w = tid >> 5;

    if (tid < TQ) s_inv[tid] = inv_from_ssq(g_ssq[qBase + tid]);

    // Load P tile with swizzle: warp w loads rows w*16..w*16+15, lane = c4.
    {
#pragma unroll
        for (int rr = 0; rr < 16; rr++) {
            int row = w * 16 + rr;
            float4 v = ((const float4*)(pool + (size_t)(pBase + row) * CC))[lane];
            int sw = (row >> 2) & 7;
            sP[row * 32 + (lane ^ sw)] = v;
        }
    }
    __syncthreads();

    // Load Q tile (L2-hot, 32 KB), scaling each row by its inverse norm.
    {
        const float4* src = (const float4*)(g_qraw + (size_t)qBase * CC);
#pragma unroll
        for (int i = 0; i < 8; i++) {
            int e = tid + i * 256;
            float inv = s_inv[e >> 5];
            float4 v = src[e];
            v.x *= inv; v.y *= inv; v.z *= inv; v.w *= inv;
            sQ[e] = v;
        }
    }
    __syncthreads();

    const ulonglong2* sQv = (const ulonglong2*)sQ;
    const ulonglong2* sPv = (const ulonglong2*)sP;

    int sw = lane & 7;                 // swizzle key for rows 4*lane..4*lane+3
    int qrow0 = w * 8;                 // this warp's 8 query rows (warp-uniform)

    unsigned long long acc[8][4];
#pragma unroll
    for (int i = 0; i < 8; i++)
#pragma unroll
        for (int j = 0; j < 4; j++) acc[i][j] = 0ULL;

#pragma unroll 4
    for (int c4 = 0; c4 < 32; c4++) {
        ulonglong2 bv[4];
#pragma unroll
        for (int j = 0; j < 4; j++)
            bv[j] = sPv[(4*lane + j) * 32 + (c4 ^ sw)];   // conflict-free
#pragma unroll
        for (int i = 0; i < 8; i++) {
            ulonglong2 av = sQv[(qrow0 + i) * 32 + c4];   // warp broadcast
#pragma unroll
            for (int j = 0; j < 4; j++) {
                fma2(acc[i][j], av.x, bv[j].x);
                fma2(acc[i][j], av.y, bv[j].y);
            }
        }
    }

    // Scale by pool inv-norm, per-query argmax across this p-tile.
    float pin[4];
#pragma unroll
    for (int j = 0; j < 4; j++) pin[j] = g_pinv[pBase + 4*lane + j];

#pragma unroll
    for (int i = 0; i < 8; i++) {
        float best = -1e30f; int bidx = 0;
#pragma unroll
        for (int j = 0; j < 4; j++) {
            float v = unpack_sum(acc[i][j]) * pin[j];
            int p = pBase + 4*lane + j;
            if (v > best) { best = v; bidx = p; }
        }
#pragma unroll
        for (int off = 16; off; off >>= 1) {
            float ov = __shfl_xor_sync(0xffffffffu, best, off);
            int   oi = __shfl_xor_sync(0xffffffffu, bidx, off);
            if (ov > best || (ov == best && oi < bidx)) { best = ov; bidx = oi; }
        }
        if (lane == 0) {
            int gq = qBase + qrow0 + i;
            g_pmax[gq * NPT + pt] = best;
            g_pidx[gq * NPT + pt] = bidx;
        }
    }
}

// ---------------------------------------------------------------------------
// K2: per-sample loss. One block per sample, one warp per logit.
// Fixed-point (2^-36) deterministic global sum; last block writes the mean.
// Also re-zeroes g_ssq[gq] so every graph replay starts from a clean state.
// ---------------------------------------------------------------------------
__global__ void k_loss(const float* __restrict__ pool,
                       const float* __restrict__ negs,
                       float* __restrict__ out) {
    int gq = blockIdx.x;
    int w = threadIdx.x >> 5, lane = threadIdx.x & 31;
    __shared__ float s_logit[8];

    float qinv = inv_from_ssq(g_ssq[gq]);
    float4 q = ((const float4*)(g_qraw + (size_t)gq * CC))[lane];
    q.x *= qinv; q.y *= qinv; q.z *= qinv; q.w *= qinv;

    if (w == 0) {
        // merge the 32 per-tile argmaxes (tie -> smallest p, jnp first-occurrence)
        float v = g_pmax[gq * NPT + lane];
        int idx = g_pidx[gq * NPT + lane];
#pragma unroll
        for (int off = 16; off; off >>= 1) {
            float ov = __shfl_xor_sync(0xffffffffu, v, off);
            int   oi = __shfl_xor_sync(0xffffffffu, idx, off);
            if (ov > v || (ov == v && oi < idx)) { v = ov; idx = oi; }
        }
        int pstar = idx;  // present in all lanes after butterfly
        float4 pp = ((const float4*)(pool + (size_t)pstar * CC))[lane];
        float d = dot4(q, pp);
#pragma unroll
        for (int off = 16; off; off >>= 1)
            d += __shfl_xor_sync(0xffffffffu, d, off);
        if (lane == 0) s_logit[0] = (d * g_pinv[pstar]) / TAU;
    } else {
        int n = w - 1;
        float4 nv = ((const float4*)(negs + ((size_t)gq * NNEG + n) * CC))[lane];
        float pd = dot4(q, nv);
        float ps = dot4(nv, nv);
#pragma unroll
        for (int off = 16; off; off >>= 1) {
            pd += __shfl_xor_sync(0xffffffffu, pd, off);
            ps += __shfl_xor_sync(0xffffffffu, ps, off);
        }
        if (lane == 0) s_logit[w] = (pd / fmaxf(sqrtf(ps), 1e-12f)) / TAU;
    }
    __syncthreads();

    if (threadIdx.x == 0) {
        float l0 = s_logit[0];
        float m = l0;
#pragma unroll
        for (int n = 1; n <= NNEG; n++) m = fmaxf(m, s_logit[n]);
        float se = 0.f;
#pragma unroll
        for (int n = 0; n <= NNEG; n++) se += expf(s_logit[n] - m);
        float loss = logf(se) - (l0 - m);

        g_ssq[gq] = 0ULL;   // reset for next graph replay (all reads done)

        // deterministic fixed-point accumulation (loss >= 0, < ~32)
        unsigned long long qv =
            (unsigned long long)__double2ll_rn((double)loss * 68719476736.0);
        atomicAdd(&g_sum, qv);
        __threadfence();
        unsigned int done = atomicAdd(&g_done, 1u);
        if (done == (unsigned int)(gridDim.x - 1)) {
            unsigned long long s = atomicAdd(&g_sum, 0ULL);
            out[0] = (float)((double)s * (1.0 / 68719476736.0) / (double)BK);
        }
    }
}

// ---------------------------------------------------------------------------
extern "C" void kernel_launch(void* const* d_in, const int* in_sizes, int n_in,
                              void* d_out, int out_size) {
    const float* qf   = (const float*)d_in[0];   // [B,C,H,W]
    const float* pool = (const float*)d_in[1];   // [P,C]
    const float* negs = (const float*)d_in[2];   // [B,K,N,C]
    const int*   qidx = (const int*)d_in[3];     // [B,K]
    float* out = (float*)d_out;

    const int smem = (TQ*CC + TP*CC) * (int)sizeof(float);   // 96 KB
    cudaFuncSetAttribute(k_sim_argmax,
                         cudaFuncAttributeMaxDynamicSharedMemorySize, smem);

    k_prep<<<272, 256>>>(pool, qf, qidx);
    k_sim_argmax<<<dim3(NQT, NPT), 256, smem>>>(pool);
    k_loss<<<BK, 256>>>(pool, negs, out);
}

// round 7
// speedup vs baseline: 2.0334x; 1.6277x over previous
#include <cuda_runtime.h>
#include <cuda_bf16.h>
#include <math.h>

// Problem constants
#define BB 8
#define CC 128
#define HH 512
#define WW 512
#define HW (HH*WW)
#define KK 64
#define BK (BB*KK)      // 512 samples
#define NNEG 7
#define PP 4096
#define TAU 0.07f

// Sim tiling: block tile 64q x 128p, K=128. 4 warps, warp tile 32q x 64p.
#define TQS 64
#define TPS 128
#define NQT (BK/TQS)    // 8
#define NPT (PP/TPS)    // 32
#define GATHER_BLOCKS 32
#define SIM_BLOCKS (NQT*NPT)           // 256
#define GRID_MAIN (GATHER_BLOCKS + SIM_BLOCKS)  // 288 <= 296 (one wave @2/SM)

// Dynamic smem layout (bytes)
#define SM_Q 0                          // 64 rows x 512B (tf32, swizzled)
#define SM_P 32768                      // 128 rows x 512B
#define SM_PINV 98304                   // 128 floats
#define SM_RV 98816                     // 2 x 64 floats
#define SM_RI 99328                     // 2 x 64 ints
#define SMEM_TOTAL 99840

// Scratch (device globals; no allocation)
__device__ float g_qraw[BK*CC];
__device__ float g_pmax[BK*NPT];
__device__ int   g_pidx[BK*NPT];
__device__ unsigned int g_qt_done[NQT];
__device__ unsigned long long g_sum;
__device__ unsigned int g_done;

__device__ __forceinline__ float dot4(float4 a, float4 b) {
    return a.x*b.x + a.y*b.y + a.z*b.z + a.w*b.w;
}

__device__ __forceinline__ unsigned tf32c(float f) {
    unsigned r;
    asm("cvt.rna.tf32.f32 %0, %1;" : "=r"(r) : "f"(f));
    return r;
}

__device__ __forceinline__ unsigned smem_u32(const void* p) {
    unsigned r;
    asm("{ .reg .u64 t; cvta.to.shared.u64 t, %1; cvt.u32.u64 %0, t; }"
        : "=r"(r) : "l"(p));
    return r;
}

__device__ __forceinline__ void ldsm4(unsigned* d, unsigned addr) {
    asm volatile("ldmatrix.sync.aligned.m8n8.x4.shared.b16 {%0,%1,%2,%3}, [%4];"
        : "=r"(d[0]), "=r"(d[1]), "=r"(d[2]), "=r"(d[3]) : "r"(addr));
}
__device__ __forceinline__ void ldsm2(unsigned* d, unsigned addr) {
    asm volatile("ldmatrix.sync.aligned.m8n8.x2.shared.b16 {%0,%1}, [%2];"
        : "=r"(d[0]), "=r"(d[1]) : "r"(addr));
}
__device__ __forceinline__ void mma_tf32(float* c, const unsigned* a, const unsigned* b) {
    asm volatile(
        "mma.sync.aligned.m16n8k8.row.col.f32.tf32.tf32.f32 "
        "{%0,%1,%2,%3}, {%4,%5,%6,%7}, {%8,%9}, {%0,%1,%2,%3};"
        : "+f"(c[0]), "+f"(c[1]), "+f"(c[2]), "+f"(c[3])
        : "r"(a[0]), "r"(a[1]), "r"(a[2]), "r"(a[3]), "r"(b[0]), "r"(b[1]));
}

// ---------------------------------------------------------------------------
// K_MAIN: blocks 0..31 gather Q pixels (DRAM-latency bound, runs first);
//         blocks 32..287 are sim blocks: load+cvt P tile, compute pool
//         inv-norms, spin on per-qt gather flag, then tf32 MMA + argmax.
// Grid 288 blocks @ 2/SM capacity 296 -> all resident in one wave: the
// spin cannot deadlock, and the P-tile prime overlaps gather latency.
// ---------------------------------------------------------------------------
__global__ void __launch_bounds__(128, 2) k_main(const float* __restrict__ qf,
                                                 const float* __restrict__ pool,
                                                 const int* __restrict__ qidx) {
    extern __shared__ char sm[];
    const unsigned smb = smem_u32(sm);
    const int bid = blockIdx.x, tid = threadIdx.x;
    const int lane = tid & 31, wid = tid >> 5;

    if (bid < GATHER_BLOCKS) {
        // ---- gather: block handles 16 samples of qt = bid>>2; warp=4 samples
        int qt = bid >> 2;
        int s0 = qt * 64 + (bid & 3) * 16 + wid * 4;
        int idx[4];
#pragma unroll
        for (int i = 0; i < 4; i++) idx[i] = qidx[s0 + i];
        float v[4][4];
#pragma unroll
        for (int i = 0; i < 4; i++) {
            const float* base = qf + ((size_t)(qt * CC + lane * 4)) * HW + idx[i];
#pragma unroll
            for (int j = 0; j < 4; j++)
                v[i][j] = __ldcs(base + (size_t)j * HW);
        }
#pragma unroll
        for (int i = 0; i < 4; i++)
            *((float4*)(g_qraw + (size_t)(s0 + i) * CC + lane * 4)) =
                make_float4(v[i][0], v[i][1], v[i][2], v[i][3]);
        __threadfence();
        __syncthreads();
        if (tid == 0) atomicAdd(&g_qt_done[qt], 1u);
        return;
    }

    // ---- sim block
    const int sb = bid - GATHER_BLOCKS;
    const int qt = sb >> 5, pt = sb & 31;
    const int qBase = qt * TQS, pBase = pt * TPS;

    // Phase 1: P tile global->smem, cvt to tf32, 32B-granule XOR swizzle.
    // row r (512B), k-step ks at ((ks ^ (r&7))<<5) + parity16.
    {
        const float4* psrc = (const float4*)(pool + (size_t)pBase * CC);
#pragma unroll
        for (int i = 0; i < 32; i++) {
            int e = tid + i * 128;           // 0..4095
            int r = e >> 5, kq = e & 31;
            float4 w = psrc[e];
            uint4 t = make_uint4(tf32c(w.x), tf32c(w.y), tf32c(w.z), tf32c(w.w));
            unsigned off = SM_P + r * 512 + ((((kq >> 1) ^ (r & 7))) << 5) + ((kq & 1) << 4);
            *((uint4*)(sm + off)) = t;
        }
    }
    __syncthreads();

    // Phase 2: pool inverse norms from smem (tf32 values are valid fp32).
    {
        int r = tid;   // 128 threads, 128 rows
        float ss = 0.f;
#pragma unroll
        for (int kq = 0; kq < 32; kq++) {
            unsigned off = SM_P + r * 512 + ((((kq >> 1) ^ (r & 7))) << 5) + ((kq & 1) << 4);
            float4 w = *((const float4*)(sm + off));
            ss += dot4(w, w);
        }
        ((float*)(sm + SM_PINV))[r] = rsqrtf(fmaxf(ss, 1e-24f));
    }

    // Phase 3: wait for this qt's gather (4 producer blocks).
    if (tid == 0) {
        while (((volatile unsigned*)g_qt_done)[qt] < 4u) __nanosleep(64);
    }
    __syncthreads();
    __threadfence();

    // Phase 4: Q tile g_qraw->smem, cvt tf32, same swizzle.
    {
        const float4* qsrc = (const float4*)(g_qraw + (size_t)qBase * CC);
#pragma unroll
        for (int i = 0; i < 16; i++) {
            int e = tid + i * 128;           // 0..2047
            int r = e >> 5, kq = e & 31;
            float4 w = qsrc[e];
            uint4 t = make_uint4(tf32c(w.x), tf32c(w.y), tf32c(w.z), tf32c(w.w));
            unsigned off = SM_Q + r * 512 + ((((kq >> 1) ^ (r & 7))) << 5) + ((kq & 1) << 4);
            *((uint4*)(sm + off)) = t;
        }
    }
    __syncthreads();

    // Phase 5: mainloop. warp (qw, pw): 32q x 64p; m16n8k8 tf32.
    const int qw = wid & 1, pw = wid >> 1;
    const int x7 = lane & 7;
    // A: lane supplies row (l&15) of its 16-row block, k-parity = l>>4
    unsigned Abase = smb + SM_Q + (unsigned)((qw * 32 + (lane & 15)) * 512) + ((lane >> 4) << 4);
    unsigned Amb1 = Abase + 16 * 512;
    // B: lanes 0..15 used; row = nb*8 + (l&7), k-parity = (l>>3)&1
    unsigned Bbase[8];
#pragma unroll
    for (int nb = 0; nb < 8; nb++)
        Bbase[nb] = smb + SM_P + (unsigned)((pw * 64 + nb * 8 + (lane & 7)) * 512) + (((lane >> 3) & 1) << 4);

    float acc[2][8][4];
#pragma unroll
    for (int mb = 0; mb < 2; mb++)
#pragma unroll
        for (int nb = 0; nb < 8; nb++)
#pragma unroll
            for (int c = 0; c < 4; c++) acc[mb][nb][c] = 0.f;

#pragma unroll
    for (int ks = 0; ks < 16; ks++) {
        unsigned koff = (unsigned)((ks ^ x7) << 5);
        unsigned a0[4], a1[4];
        ldsm4(a0, Abase + koff);
        ldsm4(a1, Amb1 + koff);
#pragma unroll
        for (int nb = 0; nb < 8; nb++) {
            unsigned bb[2];
            ldsm2(bb, Bbase[nb] + koff);
            mma_tf32(acc[0][nb], a0, bb);
            mma_tf32(acc[1][nb], a1, bb);
        }
    }

    // Phase 6: epilogue — scale by pinv, per-q argmax over this 128-p tile.
    const float* s_pinv = (const float*)(sm + SM_PINV);
    float* s_rv = (float*)(sm + SM_RV);
    int*   s_ri = (int*)(sm + SM_RI);
#pragma unroll
    for (int mb = 0; mb < 2; mb++) {
#pragma unroll
        for (int half = 0; half < 2; half++) {
            int q_blk = qw * 32 + mb * 16 + (lane >> 2) + half * 8;
            float best = -1e30f; int bi = 0;
#pragma unroll
            for (int nb = 0; nb < 8; nb++) {
#pragma unroll
                for (int c2 = 0; c2 < 2; c2++) {
                    int pl = pw * 64 + nb * 8 + (lane & 3) * 2 + c2;
                    float v = acc[mb][nb][half * 2 + c2] * s_pinv[pl];
                    int pg = pBase + pl;
                    if (v > best) { best = v; bi = pg; }
                }
            }
#pragma unroll
            for (int off = 1; off < 4; off <<= 1) {
                float ov = __shfl_xor_sync(0xffffffffu, best, off);
                int   oi = __shfl_xor_sync(0xffffffffu, bi, off);
                if (ov > best || (ov == best && oi < bi)) { best = ov; bi = oi; }
            }
            if ((lane & 3) == 0) {
                s_rv[pw * 64 + q_blk] = best;
                s_ri[pw * 64 + q_blk] = bi;
            }
        }
    }
    __syncthreads();
    if (tid < 64) {
        float v0 = s_rv[tid], v1 = s_rv[64 + tid];
        int   i0 = s_ri[tid], i1 = s_ri[64 + tid];
        float bv; int bi;
        if (v1 > v0 || (v1 == v0 && i1 < i0)) { bv = v1; bi = i1; }
        else                                   { bv = v0; bi = i0; }
        int gq = qBase + tid;
        g_pmax[gq * NPT + pt] = bv;
        g_pidx[gq * NPT + pt] = bi;
    }
}

// ---------------------------------------------------------------------------
// K_LOSS: one block per sample, warp per logit. All norms recomputed in fp32
// (exact math, independent of tf32 argmax path). Deterministic fixed-point
// sum; last block writes mean and resets all cross-launch scratch.
// ---------------------------------------------------------------------------
__global__ void k_loss(const float* __restrict__ pool,
                       const float* __restrict__ negs,
                       float* __restrict__ out) {
    int gq = blockIdx.x;
    int w = threadIdx.x >> 5, lane = threadIdx.x & 31;
    __shared__ float s_logit[8];

    float4 q = ((const float4*)(g_qraw + (size_t)gq * CC))[lane];

    if (w == 0) {
        // merge 32 per-tile argmaxes (tie -> smallest p = first occurrence)
        float v = g_pmax[gq * NPT + lane];
        int idx = g_pidx[gq * NPT + lane];
#pragma unroll
        for (int off = 16; off; off >>= 1) {
            float ov = __shfl_xor_sync(0xffffffffu, v, off);
            int   oi = __shfl_xor_sync(0xffffffffu, idx, off);
            if (ov > v || (ov == v && oi < idx)) { v = ov; idx = oi; }
        }
        int pstar = idx;
        float4 pp = ((const float4*)(pool + (size_t)pstar * CC))[lane];
        float d  = dot4(q, pp);
        float qs = dot4(q, q);
        float ps = dot4(pp, pp);
#pragma unroll
        for (int off = 16; off; off >>= 1) {
            d  += __shfl_xor_sync(0xffffffffu, d, off);
            qs += __shfl_xor_sync(0xffffffffu, qs, off);
            ps += __shfl_xor_sync(0xffffffffu, ps, off);
        }
        if (lane == 0) {
            float qinv = 1.0f / fmaxf(sqrtf(qs), 1e-12f);
            float pinv = 1.0f / fmaxf(sqrtf(ps), 1e-12f);
            s_logit[0] = (d * qinv * pinv) / TAU;
        }
    } else {
        int n = w - 1;
        float4 nv = ((const float4*)(negs + ((size_t)gq * NNEG + n) * CC))[lane];
        float pd = dot4(q, nv);
        float ns = dot4(nv, nv);
        float qs = dot4(q, q);
#pragma unroll
        for (int off = 16; off; off >>= 1) {
            pd += __shfl_xor_sync(0xffffffffu, pd, off);
            ns += __shfl_xor_sync(0xffffffffu, ns, off);
            qs += __shfl_xor_sync(0xffffffffu, qs, off);
        }
        if (lane == 0) {
            float qinv = 1.0f / fmaxf(sqrtf(qs), 1e-12f);
            s_logit[w] = (pd * qinv / fmaxf(sqrtf(ns), 1e-12f)) / TAU;
        }
    }
    __syncthreads();

    if (threadIdx.x == 0) {
        float l0 = s_logit[0];
        float m = l0;
#pragma unroll
        for (int n = 1; n <= NNEG; n++) m = fmaxf(m, s_logit[n]);
        float se = 0.f;
#pragma unroll
        for (int n = 0; n <= NNEG; n++) se += expf(s_logit[n] - m);
        float loss = logf(se) - (l0 - m);

        unsigned long long qv =
            (unsigned long long)__double2ll_rn((double)loss * 68719476736.0);
        atomicAdd(&g_sum, qv);
        __threadfence();
        unsigned int done = atomicAdd(&g_done, 1u);
        if (done == (unsigned int)(gridDim.x - 1)) {
            unsigned long long s = atomicAdd(&g_sum, 0ULL);
            out[0] = (float)((double)s * (1.0 / 68719476736.0) / (double)BK);
            // reset cross-launch scratch for the next graph replay
            g_sum = 0ULL;
            g_done = 0u;
#pragma unroll
            for (int i = 0; i < NQT; i++) g_qt_done[i] = 0u;
        }
    }
}

// ---------------------------------------------------------------------------
extern "C" void kernel_launch(void* const* d_in, const int* in_sizes, int n_in,
                              void* d_out, int out_size) {
    const float* qf   = (const float*)d_in[0];   // [B,C,H,W]
    const float* pool = (const float*)d_in[1];   // [P,C]
    const float* negs = (const float*)d_in[2];   // [B,K,N,C]
    const int*   qidx = (const int*)d_in[3];     // [B,K]
    float* out = (float*)d_out;

    cudaFuncSetAttribute(k_main,
                         cudaFuncAttributeMaxDynamicSharedMemorySize, SMEM_TOTAL);

    k_main<<<GRID_MAIN, 128, SMEM_TOTAL>>>(qf, pool, qidx);
    k_loss<<<BK, 256>>>(pool, negs, out);
}